// round 5
// baseline (speedup 1.0000x reference)
#include <cuda_runtime.h>
#include <cuda/atomic>

#define NSEQ 16384
#define HDIM 512
#define GDIM 2048
#define NCTA 128
#define TPB  256

// Scratch (device globals: no allocation allowed)
__device__ float g_XE[(size_t)NSEQ * GDIM];   // encoder x-part, bias folded
__device__ float g_XD[(size_t)NSEQ * GDIM];   // decoder x-part rows 1..N-1, bias folded
__device__ float g_h[2 * HDIM];               // double-buffered hidden state
__device__ unsigned g_leaf[16 * 32];          // 16 leaf counters, one 128B line each
__device__ unsigned g_root[32];               // root counter (own line)
__device__ unsigned g_epoch[32];              // broadcast epoch word (own line)

// ---------------------------------------------------------------------------
// init: zero h0, counters, epoch (graph-capture-safe)
// ---------------------------------------------------------------------------
__global__ void init_kernel() {
    int t = threadIdx.x;
    if (t < 2 * HDIM) g_h[t] = 0.f;
    if (t < 16 * 32) g_leaf[t] = 0u;
    if (t < 32) { g_root[t] = 0u; g_epoch[t] = 0u; }
}

// ---------------------------------------------------------------------------
// GEMM: OUT[m][n] = sum_k A[m][ak(k)] * W[n][k] + b1[n] + b2[n]
// FLIP reverses A's feature index (decoder input), targets g_XD rows 1..N-1.
// ---------------------------------------------------------------------------
template <bool FLIP>
__global__ __launch_bounds__(256, 2) void gemm_xpart(
    const float* __restrict__ A, const float* __restrict__ W,
    const float* __restrict__ b1, const float* __restrict__ b2, int Mlim)
{
    __shared__ float As[16][132];
    __shared__ float Ws[16][132];
    float* OUT = FLIP ? (g_XD + GDIM) : g_XE;

    const int bn = blockIdx.x, bm = blockIdx.y;
    const int tid = threadIdx.x;
    const int tx = tid & 15, ty = tid >> 4;

    float acc[8][8];
#pragma unroll
    for (int i = 0; i < 8; i++)
#pragma unroll
        for (int j = 0; j < 8; j++) acc[i][j] = 0.f;

    for (int k0 = 0; k0 < 512; k0 += 16) {
#pragma unroll
        for (int l = 0; l < 2; l++) {
            int fid = tid + l * 256;
            int r = fid >> 2, c4 = fid & 3;
            int gm = bm * 128 + r;
            float4 v = make_float4(0.f, 0.f, 0.f, 0.f);
            if (gm < Mlim) {
                if (!FLIP) {
                    v = *(const float4*)(A + (size_t)gm * 512 + k0 + c4 * 4);
                } else {
                    float4 w = *(const float4*)(A + (size_t)gm * 512 + (508 - k0 - c4 * 4));
                    v = make_float4(w.w, w.z, w.y, w.x);
                }
            }
            As[c4 * 4 + 0][r] = v.x; As[c4 * 4 + 1][r] = v.y;
            As[c4 * 4 + 2][r] = v.z; As[c4 * 4 + 3][r] = v.w;
        }
#pragma unroll
        for (int l = 0; l < 2; l++) {
            int fid = tid + l * 256;
            int r = fid >> 2, c4 = fid & 3;
            int gn = bn * 128 + r;
            float4 v = *(const float4*)(W + (size_t)gn * 512 + k0 + c4 * 4);
            Ws[c4 * 4 + 0][r] = v.x; Ws[c4 * 4 + 1][r] = v.y;
            Ws[c4 * 4 + 2][r] = v.z; Ws[c4 * 4 + 3][r] = v.w;
        }
        __syncthreads();
#pragma unroll
        for (int k = 0; k < 16; k++) {
            float ra[8], rb[8];
#pragma unroll
            for (int i = 0; i < 8; i++) ra[i] = As[k][ty * 8 + i];
#pragma unroll
            for (int j = 0; j < 8; j++) rb[j] = Ws[k][tx * 8 + j];
#pragma unroll
            for (int i = 0; i < 8; i++)
#pragma unroll
                for (int j = 0; j < 8; j++) acc[i][j] = fmaf(ra[i], rb[j], acc[i][j]);
        }
        __syncthreads();
    }

    float bj[8];
#pragma unroll
    for (int j = 0; j < 8; j++) {
        int gn = bn * 128 + tx * 8 + j;
        bj[j] = b1[gn] + b2[gn];
    }
#pragma unroll
    for (int i = 0; i < 8; i++) {
        int gm = bm * 128 + ty * 8 + i;
        if (gm < Mlim) {
            float* o = OUT + (size_t)gm * GDIM + bn * 128 + tx * 8;
            *(float4*)(o) = make_float4(acc[i][0] + bj[0], acc[i][1] + bj[1],
                                        acc[i][2] + bj[2], acc[i][3] + bj[3]);
            *(float4*)(o + 4) = make_float4(acc[i][4] + bj[4], acc[i][5] + bj[5],
                                            acc[i][6] + bj[6], acc[i][7] + bj[7]);
        }
    }
}

// ---------------------------------------------------------------------------
// Persistent recurrent scan — R1-proven structure; only the barrier changed:
// hierarchical arrive (16 leaf counters x 8 CTAs -> root x 16) + epoch word.
// CTA c owns hidden units [4c, 4c+4). Thread t: row li=t/16 (gate=li/4,
// unit=li%4), k-segment seg=t%16 covering 32 of the 512 h elements.
// ---------------------------------------------------------------------------
__device__ __forceinline__ float sigm_(float x) { return 1.f / (1.f + __expf(-x)); }
__device__ __forceinline__ float tanh_(float x) { return 2.f / (1.f + __expf(-2.f * x)) - 1.f; }

__global__ __launch_bounds__(TPB, 1) void lstm_scan(
    const float* __restrict__ Whh_e, const float* __restrict__ Whh_d,
    const float* __restrict__ Wih_d, const float* __restrict__ bih_d,
    const float* __restrict__ bhh_d, float* __restrict__ out)
{
    const int cta = blockIdx.x;
    const int t = threadIdx.x;
    const int li = t >> 4, seg = t & 15;
    const int gate = li >> 2, u = li & 3;
    const int grow = gate * HDIM + cta * 4 + u;   // gate-row in [0,2048)

    // Recurrent weights: 32 enc + 32 dec floats per thread, in registers.
    float we[32], wd[32];
    {
        const float4* pe = (const float4*)(Whh_e + (size_t)grow * HDIM + seg * 32);
        const float4* pd = (const float4*)(Whh_d + (size_t)grow * HDIM + seg * 32);
#pragma unroll
        for (int i = 0; i < 8; i++) {
            float4 a = pe[i];
            we[4 * i] = a.x; we[4 * i + 1] = a.y; we[4 * i + 2] = a.z; we[4 * i + 3] = a.w;
            float4 b = pd[i];
            wd[4 * i] = b.x; wd[4 * i + 1] = b.y; wd[4 * i + 2] = b.z; wd[4 * i + 3] = b.w;
        }
    }

    __shared__ float sh[HDIM];
    __shared__ float sred[16];
    __shared__ float sx[16];

    float c = 0.f;  // cell state, valid in lanes t<4 (unit = t)

    const int pg = t >> 2, pu = t & 3;            // x-part prefetch mapping (t<16)
    const int pcol = pg * HDIM + cta * 4 + pu;

    cuda::atomic_ref<unsigned, cuda::thread_scope_device> leaf(g_leaf[(cta >> 3) * 32]);
    cuda::atomic_ref<unsigned, cuda::thread_scope_device> root(g_root[0]);
    cuda::atomic_ref<unsigned, cuda::thread_scope_device> epoch(g_epoch[0]);

#pragma unroll 1
    for (int step = 1; step <= 2 * NSEQ; ++step) {
        const bool dec = step > NSEQ;
        const int s = dec ? step - NSEQ : step;
        const bool xd0 = dec && (s == 1);

        // Prefetch x-part for this step (independent of h; overlaps the spin)
        float xv = 0.f;
        if (t < 16 && !xd0) {
            const float* xb = dec ? (g_XD + (size_t)(s - 1) * GDIM)
                                  : (g_XE + (size_t)(s - 1) * GDIM);
            xv = __ldg(xb + pcol);
        }

        // Wait until all CTAs published h_{step-1}: poll the epoch word only.
        if (t == 0 && step > 1) {
            while (epoch.load(cuda::memory_order_acquire) < (unsigned)(step - 1)) { }
        }
        __syncthreads();                                  // sync A

        // Load h_{step-1} into SMEM (L2-fresh via .cg)
        const float* hb = g_h + ((step - 1) & 1) * HDIM;
        if (t < 128) {
            float4 hv = __ldcg((const float4*)hb + t);
            ((float4*)sh)[t] = hv;
        }
        if (t < 16) sx[t] = xv;
        __syncthreads();                                  // sync B

        // Partial dot: 32 MACs against register weights
        float a0 = 0.f, a1 = 0.f, a2 = 0.f, a3 = 0.f;
        const float4* sh4 = (const float4*)sh + seg * 8;
        if (!dec) {
#pragma unroll
            for (int i = 0; i < 8; i++) {
                float4 h4 = sh4[i];
                a0 = fmaf(we[4 * i], h4.x, a0);
                a1 = fmaf(we[4 * i + 1], h4.y, a1);
                a2 = fmaf(we[4 * i + 2], h4.z, a2);
                a3 = fmaf(we[4 * i + 3], h4.w, a3);
            }
        } else {
#pragma unroll
            for (int i = 0; i < 8; i++) {
                float4 h4 = sh4[i];
                a0 = fmaf(wd[4 * i], h4.x, a0);
                a1 = fmaf(wd[4 * i + 1], h4.y, a1);
                a2 = fmaf(wd[4 * i + 2], h4.z, a2);
                a3 = fmaf(wd[4 * i + 3], h4.w, a3);
            }
        }
        float sum = (a0 + a1) + (a2 + a3);

        // Decoder step 1: input is h_n itself -> add Wih_d . h_n inline
        if (xd0) {
            const float4* pw = (const float4*)(Wih_d + (size_t)grow * HDIM + seg * 32);
            float c0 = 0.f, c1 = 0.f, c2 = 0.f, c3 = 0.f;
#pragma unroll
            for (int i = 0; i < 8; i++) {
                float4 w4 = pw[i];
                float4 h4 = sh4[i];
                c0 = fmaf(w4.x, h4.x, c0);
                c1 = fmaf(w4.y, h4.y, c1);
                c2 = fmaf(w4.z, h4.z, c2);
                c3 = fmaf(w4.w, h4.w, c3);
            }
            sum += (c0 + c1) + (c2 + c3);
        }

        // Reduce over 16 k-segments (two independent 16-lane halves per warp)
        sum += __shfl_xor_sync(0xffffffffu, sum, 1);
        sum += __shfl_xor_sync(0xffffffffu, sum, 2);
        sum += __shfl_xor_sync(0xffffffffu, sum, 4);
        sum += __shfl_xor_sync(0xffffffffu, sum, 8);
        if (seg == 0) sred[li] = sum;
        __syncthreads();                                  // sync C

        // Lanes 0..3 (unit u = t): gates -> c,h update -> publish via t0
        if (t < 4) {
            float xi = sx[t], xf = sx[4 + t], xg = sx[8 + t], xo = sx[12 + t];
            if (xd0) {  // bias not folded for the locally-computed row 0
                int base = cta * 4 + t;
                xi = __ldg(bih_d + base)        + __ldg(bhh_d + base);
                xf = __ldg(bih_d + 512 + base)  + __ldg(bhh_d + 512 + base);
                xg = __ldg(bih_d + 1024 + base) + __ldg(bhh_d + 1024 + base);
                xo = __ldg(bih_d + 1536 + base) + __ldg(bhh_d + 1536 + base);
            }
            float gi = sigm_(sred[t] + xi);
            float gf = sigm_(sred[4 + t] + xf);
            float gg = tanh_(sred[8 + t] + xg);
            float go = sigm_(sred[12 + t] + xo);
            c = fmaf(gf, c, gi * gg);
            float hn = go * tanh_(c);

            const int j = cta * 4 + t;
            if (dec) {
                out[HDIM + (size_t)(s - 1) * HDIM + (HDIM - 1 - j)] = hn;  // feature flip
            } else if (step == NSEQ) {
                out[j] = hn;  // h_n
            }

            // Gather the CTA's 4 h values into lane 0; t0 stores + arrives so
            // release ordering covers the h store formally (single thread).
            float4 pub;
            pub.x = __shfl_sync(0xFu, hn, 0);
            pub.y = __shfl_sync(0xFu, hn, 1);
            pub.z = __shfl_sync(0xFu, hn, 2);
            pub.w = __shfl_sync(0xFu, hn, 3);
            if (t == 0) {
                __stcg(((float4*)g_h) + (step & 1) * 128 + cta, pub);
                unsigned old = leaf.fetch_add(1u, cuda::memory_order_acq_rel);
                if ((old & 7u) == 7u) {                   // last of 8 on this leaf
                    unsigned oldr = root.fetch_add(1u, cuda::memory_order_acq_rel);
                    if ((oldr & 15u) == 15u)              // last of 16 leaves
                        epoch.store((unsigned)step, cuda::memory_order_release);
                }
            }
        }
        __syncthreads();                                  // sync D
    }
}

// ---------------------------------------------------------------------------
extern "C" void kernel_launch(void* const* d_in, const int* in_sizes, int n_in,
                              void* d_out, int out_size)
{
    const float* x     = (const float*)d_in[0];
    const float* Wih_e = (const float*)d_in[1];
    const float* Whh_e = (const float*)d_in[2];
    const float* bih_e = (const float*)d_in[3];
    const float* bhh_e = (const float*)d_in[4];
    const float* Wih_d = (const float*)d_in[5];
    const float* Whh_d = (const float*)d_in[6];
    const float* bih_d = (const float*)d_in[7];
    const float* bhh_d = (const float*)d_in[8];
    float* out = (float*)d_out;

    init_kernel<<<1, 1024>>>();

    dim3 gg(GDIM / 128, NSEQ / 128);
    gemm_xpart<false><<<gg, 256>>>(x, Wih_e, bih_e, bhh_e, NSEQ);
    gemm_xpart<true ><<<gg, 256>>>(x, Wih_d, bih_d, bhh_d, NSEQ - 1);

    lstm_scan<<<NCTA, TPB>>>(Whh_e, Whh_d, Wih_d, bih_d, bhh_d, out);
}

// round 7
// speedup vs baseline: 1.5027x; 1.5027x over previous
#include <cuda_runtime.h>
#include <cuda/atomic>

#define NSEQ 16384
#define HDIM 512
#define GDIM 2048
#define NCTA 128
#define TPB  256

// Scratch (device globals: no allocation allowed)
__device__ float g_XE[(size_t)NSEQ * GDIM];   // encoder x-part, bias folded
__device__ float g_XD[(size_t)NSEQ * GDIM];   // decoder x-part rows 1..N-1, bias folded
__device__ unsigned long long g_pair[2][HDIM]; // {h_bits:32 | epoch:32} per unit, x2 parity

// ---------------------------------------------------------------------------
// init: parity 0 = {h=0.0f, epoch=0} (valid h_0); parity 1 = epoch ~0 (never
// matches an expected epoch 1..2N). Graph-capture-safe.
// ---------------------------------------------------------------------------
__global__ void init_kernel() {
    int t = threadIdx.x;
    if (t < HDIM) {
        g_pair[0][t] = 0ull;                       // h bits 0.0f, epoch 0
        g_pair[1][t] = 0x00000000FFFFFFFFull;      // epoch 0xFFFFFFFF
    }
}

// ---------------------------------------------------------------------------
// GEMM: OUT[m][n] = sum_k A[m][ak(k)] * W[n][k] + b1[n] + b2[n]
// FLIP reverses A's feature index (decoder input), targets g_XD rows 1..N-1.
// ---------------------------------------------------------------------------
template <bool FLIP>
__global__ __launch_bounds__(256, 2) void gemm_xpart(
    const float* __restrict__ A, const float* __restrict__ W,
    const float* __restrict__ b1, const float* __restrict__ b2, int Mlim)
{
    __shared__ float As[16][132];
    __shared__ float Ws[16][132];
    float* OUT = FLIP ? (g_XD + GDIM) : g_XE;

    const int bn = blockIdx.x, bm = blockIdx.y;
    const int tid = threadIdx.x;
    const int tx = tid & 15, ty = tid >> 4;

    float acc[8][8];
#pragma unroll
    for (int i = 0; i < 8; i++)
#pragma unroll
        for (int j = 0; j < 8; j++) acc[i][j] = 0.f;

    for (int k0 = 0; k0 < 512; k0 += 16) {
#pragma unroll
        for (int l = 0; l < 2; l++) {
            int fid = tid + l * 256;
            int r = fid >> 2, c4 = fid & 3;
            int gm = bm * 128 + r;
            float4 v = make_float4(0.f, 0.f, 0.f, 0.f);
            if (gm < Mlim) {
                if (!FLIP) {
                    v = *(const float4*)(A + (size_t)gm * 512 + k0 + c4 * 4);
                } else {
                    float4 w = *(const float4*)(A + (size_t)gm * 512 + (508 - k0 - c4 * 4));
                    v = make_float4(w.w, w.z, w.y, w.x);
                }
            }
            As[c4 * 4 + 0][r] = v.x; As[c4 * 4 + 1][r] = v.y;
            As[c4 * 4 + 2][r] = v.z; As[c4 * 4 + 3][r] = v.w;
        }
#pragma unroll
        for (int l = 0; l < 2; l++) {
            int fid = tid + l * 256;
            int r = fid >> 2, c4 = fid & 3;
            int gn = bn * 128 + r;
            float4 v = *(const float4*)(W + (size_t)gn * 512 + k0 + c4 * 4);
            Ws[c4 * 4 + 0][r] = v.x; Ws[c4 * 4 + 1][r] = v.y;
            Ws[c4 * 4 + 2][r] = v.z; Ws[c4 * 4 + 3][r] = v.w;
        }
        __syncthreads();
#pragma unroll
        for (int k = 0; k < 16; k++) {
            float ra[8], rb[8];
#pragma unroll
            for (int i = 0; i < 8; i++) ra[i] = As[k][ty * 8 + i];
#pragma unroll
            for (int j = 0; j < 8; j++) rb[j] = Ws[k][tx * 8 + j];
#pragma unroll
            for (int i = 0; i < 8; i++)
#pragma unroll
                for (int j = 0; j < 8; j++) acc[i][j] = fmaf(ra[i], rb[j], acc[i][j]);
        }
        __syncthreads();
    }

    float bj[8];
#pragma unroll
    for (int j = 0; j < 8; j++) {
        int gn = bn * 128 + tx * 8 + j;
        bj[j] = b1[gn] + b2[gn];
    }
#pragma unroll
    for (int i = 0; i < 8; i++) {
        int gm = bm * 128 + ty * 8 + i;
        if (gm < Mlim) {
            float* o = OUT + (size_t)gm * GDIM + bn * 128 + tx * 8;
            *(float4*)(o) = make_float4(acc[i][0] + bj[0], acc[i][1] + bj[1],
                                        acc[i][2] + bj[2], acc[i][3] + bj[3]);
            *(float4*)(o + 4) = make_float4(acc[i][4] + bj[4], acc[i][5] + bj[5],
                                            acc[i][6] + bj[6], acc[i][7] + bj[7]);
        }
    }
}

// ---------------------------------------------------------------------------
// Persistent recurrent scan. Sync = epoch-tagged 64-bit {h|epoch} pairs held
// in MORALLY-STRONG atomics (the weak-.cg variants are torn/unordered on
// sm_100a — R2/R3/R4/R6 evidence). Flag and data share one word: depth-1
// round trip, no counters, no fences. CTA c owns hidden units [4c, 4c+4).
// Thread t: row li=t/16 (gate=li/4, unit=li%4), k-segment seg=t%16.
// ---------------------------------------------------------------------------
__device__ __forceinline__ float sigm_(float x) { return 1.f / (1.f + __expf(-x)); }
__device__ __forceinline__ float tanh_(float x) { return 2.f / (1.f + __expf(-2.f * x)) - 1.f; }

__global__ __launch_bounds__(TPB, 1) void lstm_scan(
    const float* __restrict__ Whh_e, const float* __restrict__ Whh_d,
    const float* __restrict__ Wih_d, const float* __restrict__ bih_d,
    const float* __restrict__ bhh_d, float* __restrict__ out)
{
    const int cta = blockIdx.x;
    const int t = threadIdx.x;
    const int li = t >> 4, seg = t & 15;
    const int gate = li >> 2, u = li & 3;
    const int grow = gate * HDIM + cta * 4 + u;   // gate-row in [0,2048)

    // Recurrent weights: 32 enc + 32 dec floats per thread, in registers.
    float we[32], wd[32];
    {
        const float4* pe = (const float4*)(Whh_e + (size_t)grow * HDIM + seg * 32);
        const float4* pd = (const float4*)(Whh_d + (size_t)grow * HDIM + seg * 32);
#pragma unroll
        for (int i = 0; i < 8; i++) {
            float4 a = pe[i];
            we[4 * i] = a.x; we[4 * i + 1] = a.y; we[4 * i + 2] = a.z; we[4 * i + 3] = a.w;
            float4 b = pd[i];
            wd[4 * i] = b.x; wd[4 * i + 1] = b.y; wd[4 * i + 2] = b.z; wd[4 * i + 3] = b.w;
        }
    }

    __shared__ __align__(16) float sh[HDIM];
    __shared__ float sred[16];
    __shared__ float sx[16];

    float c = 0.f;  // cell state, valid in lanes t<4 (unit = t)

    const int pg = t >> 2, pu = t & 3;            // x-part prefetch mapping (t<16)
    const int pcol = pg * HDIM + cta * 4 + pu;

#pragma unroll 1
    for (int step = 1; step <= 2 * NSEQ; ++step) {
        const bool dec = step > NSEQ;
        const int s = dec ? step - NSEQ : step;
        const bool xd0 = dec && (s == 1);

        // Prefetch x-part for this step (independent of h; overlaps the poll)
        float xv = 0.f;
        if (t < 16 && !xd0) {
            const float* xb = dec ? (g_XD + (size_t)(s - 1) * GDIM)
                                  : (g_XE + (size_t)(s - 1) * GDIM);
            xv = __ldg(xb + pcol);
        }

        // Poll h_{step-1}: each thread owns 2 pairs. Strong relaxed atomic
        // loads; accept on exact epoch match (data travels inside the word,
        // so no further ordering is required).
        {
            const unsigned exp = (unsigned)(step - 1);
            cuda::atomic_ref<unsigned long long, cuda::thread_scope_device>
                p0(g_pair[(step - 1) & 1][2 * t]);
            cuda::atomic_ref<unsigned long long, cuda::thread_scope_device>
                p1(g_pair[(step - 1) & 1][2 * t + 1]);
            unsigned long long v0 = p0.load(cuda::memory_order_relaxed);
            unsigned long long v1 = p1.load(cuda::memory_order_relaxed);
            while ((unsigned)v0 != exp || (unsigned)v1 != exp) {
                v0 = p0.load(cuda::memory_order_relaxed);
                v1 = p1.load(cuda::memory_order_relaxed);
            }
            sh[2 * t]     = __uint_as_float((unsigned)(v0 >> 32));
            sh[2 * t + 1] = __uint_as_float((unsigned)(v1 >> 32));
        }
        if (t < 16) sx[t] = xv;
        __syncthreads();                                  // sync 1: sh/sx ready

        // Partial dot: 32 MACs against register weights
        float a0 = 0.f, a1 = 0.f, a2 = 0.f, a3 = 0.f;
        const float4* sh4 = (const float4*)sh + seg * 8;
        if (!dec) {
#pragma unroll
            for (int i = 0; i < 8; i++) {
                float4 h4 = sh4[i];
                a0 = fmaf(we[4 * i], h4.x, a0);
                a1 = fmaf(we[4 * i + 1], h4.y, a1);
                a2 = fmaf(we[4 * i + 2], h4.z, a2);
                a3 = fmaf(we[4 * i + 3], h4.w, a3);
            }
        } else {
#pragma unroll
            for (int i = 0; i < 8; i++) {
                float4 h4 = sh4[i];
                a0 = fmaf(wd[4 * i], h4.x, a0);
                a1 = fmaf(wd[4 * i + 1], h4.y, a1);
                a2 = fmaf(wd[4 * i + 2], h4.z, a2);
                a3 = fmaf(wd[4 * i + 3], h4.w, a3);
            }
        }
        float sum = (a0 + a1) + (a2 + a3);

        // Decoder step 1: input is h_n itself -> add Wih_d . h_n inline
        if (xd0) {
            const float4* pw = (const float4*)(Wih_d + (size_t)grow * HDIM + seg * 32);
            float c0 = 0.f, c1 = 0.f, c2 = 0.f, c3 = 0.f;
#pragma unroll
            for (int i = 0; i < 8; i++) {
                float4 w4 = pw[i];
                float4 h4 = sh4[i];
                c0 = fmaf(w4.x, h4.x, c0);
                c1 = fmaf(w4.y, h4.y, c1);
                c2 = fmaf(w4.z, h4.z, c2);
                c3 = fmaf(w4.w, h4.w, c3);
            }
            sum += (c0 + c1) + (c2 + c3);
        }

        // Reduce over 16 k-segments (two independent 16-lane halves per warp)
        sum += __shfl_xor_sync(0xffffffffu, sum, 1);
        sum += __shfl_xor_sync(0xffffffffu, sum, 2);
        sum += __shfl_xor_sync(0xffffffffu, sum, 4);
        sum += __shfl_xor_sync(0xffffffffu, sum, 8);
        if (seg == 0) sred[li] = sum;
        __syncthreads();                                  // sync 2: sred ready

        // Lanes 0..3 (unit u = t): gates -> c,h update -> publish epoch pair
        if (t < 4) {
            float xi = sx[t], xf = sx[4 + t], xg = sx[8 + t], xo = sx[12 + t];
            if (xd0) {  // bias not folded for the locally-computed row 0
                int base = cta * 4 + t;
                xi = __ldg(bih_d + base)        + __ldg(bhh_d + base);
                xf = __ldg(bih_d + 512 + base)  + __ldg(bhh_d + 512 + base);
                xg = __ldg(bih_d + 1024 + base) + __ldg(bhh_d + 1024 + base);
                xo = __ldg(bih_d + 1536 + base) + __ldg(bhh_d + 1536 + base);
            }
            float gi = sigm_(sred[t] + xi);
            float gf = sigm_(sred[4 + t] + xf);
            float gg = tanh_(sred[8 + t] + xg);
            float go = sigm_(sred[12 + t] + xo);
            c = fmaf(gf, c, gi * gg);
            float hn = go * tanh_(c);

            const int j = cta * 4 + t;
            if (dec) {
                out[HDIM + (size_t)(s - 1) * HDIM + (HDIM - 1 - j)] = hn;  // feature flip
            } else if (step == NSEQ) {
                out[j] = hn;  // h_n
            }

            // Publish {h | epoch} as ONE strong release store — flag IS data.
            unsigned long long pv =
                ((unsigned long long)__float_as_uint(hn) << 32) | (unsigned)step;
            cuda::atomic_ref<unsigned long long, cuda::thread_scope_device>
                pj(g_pair[step & 1][j]);
            pj.store(pv, cuda::memory_order_release);
        }
        __syncthreads();                                  // sync 3: protect sx/sh
    }
}

// ---------------------------------------------------------------------------
extern "C" void kernel_launch(void* const* d_in, const int* in_sizes, int n_in,
                              void* d_out, int out_size)
{
    const float* x     = (const float*)d_in[0];
    const float* Wih_e = (const float*)d_in[1];
    const float* Whh_e = (const float*)d_in[2];
    const float* bih_e = (const float*)d_in[3];
    const float* bhh_e = (const float*)d_in[4];
    const float* Wih_d = (const float*)d_in[5];
    const float* Whh_d = (const float*)d_in[6];
    const float* bih_d = (const float*)d_in[7];
    const float* bhh_d = (const float*)d_in[8];
    float* out = (float*)d_out;

    init_kernel<<<1, 1024>>>();

    dim3 gg(GDIM / 128, NSEQ / 128);
    gemm_xpart<false><<<gg, 256>>>(x, Wih_e, bih_e, bhh_e, NSEQ);
    gemm_xpart<true ><<<gg, 256>>>(x, Wih_d, bih_d, bhh_d, NSEQ - 1);

    lstm_scan<<<NCTA, TPB>>>(Whh_e, Whh_d, Wih_d, bih_d, bhh_d, out);
}

// round 8
// speedup vs baseline: 1.5358x; 1.0220x over previous
#include <cuda_runtime.h>
#include <cuda/atomic>

#define NSEQ 16384
#define HDIM 512
#define GDIM 2048
#define NCTA 128
#define TPB  256

// Scratch (device globals: no allocation allowed)
__device__ float g_XE[(size_t)NSEQ * GDIM];   // encoder x-part, bias folded
__device__ float g_XD[(size_t)NSEQ * GDIM];   // decoder x-part rows 1..N-1, bias folded
__device__ unsigned long long g_pair[2][HDIM]; // {h_bits:32 | epoch:32} per unit, x2 parity

// ---------------------------------------------------------------------------
// init: parity 0 = {h=0.0f, epoch=0} (valid h_0); parity 1 = epoch ~0 (never
// matches an expected epoch 1..2N). Graph-capture-safe.
// ---------------------------------------------------------------------------
__global__ void init_kernel() {
    int t = threadIdx.x;
    if (t < HDIM) {
        g_pair[0][t] = 0ull;                       // h bits 0.0f, epoch 0
        g_pair[1][t] = 0x00000000FFFFFFFFull;      // epoch 0xFFFFFFFF
    }
}

// ---------------------------------------------------------------------------
// GEMM: OUT[m][n] = sum_k A[m][ak(k)] * W[n][k] + b1[n] + b2[n]
// FLIP reverses A's feature index (decoder input), targets g_XD rows 1..N-1.
// ---------------------------------------------------------------------------
template <bool FLIP>
__global__ __launch_bounds__(256, 2) void gemm_xpart(
    const float* __restrict__ A, const float* __restrict__ W,
    const float* __restrict__ b1, const float* __restrict__ b2, int Mlim)
{
    __shared__ float As[16][132];
    __shared__ float Ws[16][132];
    float* OUT = FLIP ? (g_XD + GDIM) : g_XE;

    const int bn = blockIdx.x, bm = blockIdx.y;
    const int tid = threadIdx.x;
    const int tx = tid & 15, ty = tid >> 4;

    float acc[8][8];
#pragma unroll
    for (int i = 0; i < 8; i++)
#pragma unroll
        for (int j = 0; j < 8; j++) acc[i][j] = 0.f;

    for (int k0 = 0; k0 < 512; k0 += 16) {
#pragma unroll
        for (int l = 0; l < 2; l++) {
            int fid = tid + l * 256;
            int r = fid >> 2, c4 = fid & 3;
            int gm = bm * 128 + r;
            float4 v = make_float4(0.f, 0.f, 0.f, 0.f);
            if (gm < Mlim) {
                if (!FLIP) {
                    v = *(const float4*)(A + (size_t)gm * 512 + k0 + c4 * 4);
                } else {
                    float4 w = *(const float4*)(A + (size_t)gm * 512 + (508 - k0 - c4 * 4));
                    v = make_float4(w.w, w.z, w.y, w.x);
                }
            }
            As[c4 * 4 + 0][r] = v.x; As[c4 * 4 + 1][r] = v.y;
            As[c4 * 4 + 2][r] = v.z; As[c4 * 4 + 3][r] = v.w;
        }
#pragma unroll
        for (int l = 0; l < 2; l++) {
            int fid = tid + l * 256;
            int r = fid >> 2, c4 = fid & 3;
            int gn = bn * 128 + r;
            float4 v = *(const float4*)(W + (size_t)gn * 512 + k0 + c4 * 4);
            Ws[c4 * 4 + 0][r] = v.x; Ws[c4 * 4 + 1][r] = v.y;
            Ws[c4 * 4 + 2][r] = v.z; Ws[c4 * 4 + 3][r] = v.w;
        }
        __syncthreads();
#pragma unroll
        for (int k = 0; k < 16; k++) {
            float ra[8], rb[8];
#pragma unroll
            for (int i = 0; i < 8; i++) ra[i] = As[k][ty * 8 + i];
#pragma unroll
            for (int j = 0; j < 8; j++) rb[j] = Ws[k][tx * 8 + j];
#pragma unroll
            for (int i = 0; i < 8; i++)
#pragma unroll
                for (int j = 0; j < 8; j++) acc[i][j] = fmaf(ra[i], rb[j], acc[i][j]);
        }
        __syncthreads();
    }

    float bj[8];
#pragma unroll
    for (int j = 0; j < 8; j++) {
        int gn = bn * 128 + tx * 8 + j;
        bj[j] = b1[gn] + b2[gn];
    }
#pragma unroll
    for (int i = 0; i < 8; i++) {
        int gm = bm * 128 + ty * 8 + i;
        if (gm < Mlim) {
            float* o = OUT + (size_t)gm * GDIM + bn * 128 + tx * 8;
            *(float4*)(o) = make_float4(acc[i][0] + bj[0], acc[i][1] + bj[1],
                                        acc[i][2] + bj[2], acc[i][3] + bj[3]);
            *(float4*)(o + 4) = make_float4(acc[i][4] + bj[4], acc[i][5] + bj[5],
                                            acc[i][6] + bj[6], acc[i][7] + bj[7]);
        }
    }
}

// ---------------------------------------------------------------------------
// Persistent recurrent scan. Sync = epoch-tagged 64-bit {h|epoch} pairs in
// strong atomics (proven R7), now with nanosleep backoff to kill the poll
// storm; activations on the 16 reduce lanes; 2 barriers/step via parity
// double-buffered sh/sred. CTA c owns hidden units [4c, 4c+4).
// Thread t: row li=t/16 (gate=li/4, unit=li%4), k-segment seg=t%16.
// ---------------------------------------------------------------------------
__device__ __forceinline__ float sigm_(float x) { return 1.f / (1.f + __expf(-x)); }
__device__ __forceinline__ float tanh_(float x) { return 2.f / (1.f + __expf(-2.f * x)) - 1.f; }

__global__ __launch_bounds__(TPB, 1) void lstm_scan(
    const float* __restrict__ Whh_e, const float* __restrict__ Whh_d,
    const float* __restrict__ Wih_d, const float* __restrict__ bih_d,
    const float* __restrict__ bhh_d, float* __restrict__ out)
{
    const int cta = blockIdx.x;
    const int t = threadIdx.x;
    const int li = t >> 4, seg = t & 15;
    const int gate = li >> 2, u = li & 3;
    const int grow = gate * HDIM + cta * 4 + u;   // gate-row in [0,2048)

    // Recurrent weights: 32 enc + 32 dec floats per thread, in registers.
    float we[32], wd[32];
    {
        const float4* pe = (const float4*)(Whh_e + (size_t)grow * HDIM + seg * 32);
        const float4* pd = (const float4*)(Whh_d + (size_t)grow * HDIM + seg * 32);
#pragma unroll
        for (int i = 0; i < 8; i++) {
            float4 a = pe[i];
            we[4 * i] = a.x; we[4 * i + 1] = a.y; we[4 * i + 2] = a.z; we[4 * i + 3] = a.w;
            float4 b = pd[i];
            wd[4 * i] = b.x; wd[4 * i + 1] = b.y; wd[4 * i + 2] = b.z; wd[4 * i + 3] = b.w;
        }
    }

    __shared__ __align__(16) float sh[2][HDIM];   // parity double-buffered h
    __shared__ float sred[2][16];                 // parity double-buffered gates

    float c = 0.f;  // cell state, valid in lanes t<4 (unit = t)

    // Reduce lane (seg==0) owns row li: it prefetches that row's x-part
    // directly into a register (no SMEM staging, no extra barrier).
    const bool rl = (seg == 0);

#pragma unroll 1
    for (int step = 1; step <= 2 * NSEQ; ++step) {
        const bool dec = step > NSEQ;
        const int s = dec ? step - NSEQ : step;
        const bool xd0 = dec && (s == 1);
        const int pc = (step - 1) & 1;            // consume parity
        const int pp = step & 1;                  // produce parity

        // Prefetch x-part (or dec-step-1 bias sum) on the reduce lanes only.
        float xv = 0.f;
        if (rl) {
            if (xd0) {
                xv = __ldg(bih_d + grow) + __ldg(bhh_d + grow);
            } else {
                const float* xb = dec ? (g_XD + (size_t)(s - 1) * GDIM)
                                      : (g_XE + (size_t)(s - 1) * GDIM);
                xv = __ldg(xb + grow);
            }
        }

        // Poll h_{step-1}: 2 strong relaxed 8B loads per thread; flag IS the
        // data. One immediate probe, then nanosleep backoff so the probe
        // storm doesn't congest L2 and delay the publishes themselves.
        {
            const unsigned exp = (unsigned)(step - 1);
            cuda::atomic_ref<unsigned long long, cuda::thread_scope_device>
                p0(g_pair[pc][2 * t]);
            cuda::atomic_ref<unsigned long long, cuda::thread_scope_device>
                p1(g_pair[pc][2 * t + 1]);
            unsigned long long v0 = p0.load(cuda::memory_order_relaxed);
            unsigned long long v1 = p1.load(cuda::memory_order_relaxed);
            while ((unsigned)v0 != exp || (unsigned)v1 != exp) {
                __nanosleep(32);
                v0 = p0.load(cuda::memory_order_relaxed);
                v1 = p1.load(cuda::memory_order_relaxed);
            }
            sh[pc][2 * t]     = __uint_as_float((unsigned)(v0 >> 32));
            sh[pc][2 * t + 1] = __uint_as_float((unsigned)(v1 >> 32));
        }
        __syncthreads();                                  // sync 1: sh ready

        // Partial dot: 32 MACs against register weights
        float a0 = 0.f, a1 = 0.f, a2 = 0.f, a3 = 0.f;
        const float4* sh4 = (const float4*)sh[pc] + seg * 8;
        if (!dec) {
#pragma unroll
            for (int i = 0; i < 8; i++) {
                float4 h4 = sh4[i];
                a0 = fmaf(we[4 * i], h4.x, a0);
                a1 = fmaf(we[4 * i + 1], h4.y, a1);
                a2 = fmaf(we[4 * i + 2], h4.z, a2);
                a3 = fmaf(we[4 * i + 3], h4.w, a3);
            }
        } else {
#pragma unroll
            for (int i = 0; i < 8; i++) {
                float4 h4 = sh4[i];
                a0 = fmaf(wd[4 * i], h4.x, a0);
                a1 = fmaf(wd[4 * i + 1], h4.y, a1);
                a2 = fmaf(wd[4 * i + 2], h4.z, a2);
                a3 = fmaf(wd[4 * i + 3], h4.w, a3);
            }
        }
        float sum = (a0 + a1) + (a2 + a3);

        // Decoder step 1: input is h_n itself -> add Wih_d . h_n inline
        if (xd0) {
            const float4* pw = (const float4*)(Wih_d + (size_t)grow * HDIM + seg * 32);
            float c0 = 0.f, c1 = 0.f, c2 = 0.f, c3 = 0.f;
#pragma unroll
            for (int i = 0; i < 8; i++) {
                float4 w4 = pw[i];
                float4 h4 = sh4[i];
                c0 = fmaf(w4.x, h4.x, c0);
                c1 = fmaf(w4.y, h4.y, c1);
                c2 = fmaf(w4.z, h4.z, c2);
                c3 = fmaf(w4.w, h4.w, c3);
            }
            sum += (c0 + c1) + (c2 + c3);
        }

        // Reduce over 16 k-segments (two independent 16-lane halves per warp)
        sum += __shfl_xor_sync(0xffffffffu, sum, 1);
        sum += __shfl_xor_sync(0xffffffffu, sum, 2);
        sum += __shfl_xor_sync(0xffffffffu, sum, 4);
        sum += __shfl_xor_sync(0xffffffffu, sum, 8);

        // Activation on the 16 reduce lanes in parallel (1 MUFU chain each,
        // spread across 8 warps). Same arithmetic order as before:
        // (raw sum) + x-part, then sigmoid/tanh.
        if (rl) {
            float red = sum + xv;
            sred[pp][li] = (gate == 2) ? tanh_(red) : sigm_(red);
        }
        __syncthreads();                                  // sync 2: sred ready

        // Lanes 0..3 (unit u = t): c,h update -> publish epoch pair
        if (t < 4) {
            float gi = sred[pp][t],     gf = sred[pp][4 + t];
            float gg = sred[pp][8 + t], go = sred[pp][12 + t];
            c = fmaf(gf, c, gi * gg);
            float hn = go * tanh_(c);

            const int j = cta * 4 + t;
            if (dec) {
                out[HDIM + (size_t)(s - 1) * HDIM + (HDIM - 1 - j)] = hn;  // feature flip
            } else if (step == NSEQ) {
                out[j] = hn;  // h_n
            }

            // Publish {h | epoch} as ONE strong release store — flag IS data.
            unsigned long long pv =
                ((unsigned long long)__float_as_uint(hn) << 32) | (unsigned)step;
            cuda::atomic_ref<unsigned long long, cuda::thread_scope_device>
                pj(g_pair[pp][j]);
            pj.store(pv, cuda::memory_order_release);
        }
        // no sync 3: parity double-buffering makes next-iter writes safe
        // (any same-parity rewrite at step+2 happens after sync1(step+2),
        //  which transitively follows every read of this step).
    }
}

// ---------------------------------------------------------------------------
extern "C" void kernel_launch(void* const* d_in, const int* in_sizes, int n_in,
                              void* d_out, int out_size)
{
    const float* x     = (const float*)d_in[0];
    const float* Wih_e = (const float*)d_in[1];
    const float* Whh_e = (const float*)d_in[2];
    const float* bih_e = (const float*)d_in[3];
    const float* bhh_e = (const float*)d_in[4];
    const float* Wih_d = (const float*)d_in[5];
    const float* Whh_d = (const float*)d_in[6];
    const float* bih_d = (const float*)d_in[7];
    const float* bhh_d = (const float*)d_in[8];
    float* out = (float*)d_out;

    init_kernel<<<1, 1024>>>();

    dim3 gg(GDIM / 128, NSEQ / 128);
    gemm_xpart<false><<<gg, 256>>>(x, Wih_e, bih_e, bhh_e, NSEQ);
    gemm_xpart<true ><<<gg, 256>>>(x, Wih_d, bih_d, bhh_d, NSEQ - 1);

    lstm_scan<<<NCTA, TPB>>>(Whh_e, Whh_d, Wih_d, bih_d, bhh_d, out);
}